// round 3
// baseline (speedup 1.0000x reference)
#include <cuda_runtime.h>

#define NVOX   (64*64*64)      // 262144 voxels
#define BKN    28              // 4 batches * 7 moving parts
#define CHUNKS 32              // reduction units per (b,k): 896 total, 32KB each
#define NUNITS (BKN * CHUNKS)  // 896
#define GRID   296             // 148 SMs * 2 — single co-resident wave
#define THREADS 256

// Scratch + barrier state (no allocations allowed)
__device__ float    g_partial[NUNITS * 4];
__device__ unsigned g_count = 0;   // self-resets each launch
__device__ unsigned g_gen   = 0;   // monotonically increasing generation

__global__ void __launch_bounds__(THREADS)
fused_k(const float* __restrict__ mask, const float* __restrict__ grids,
        const float* __restrict__ trans_vec, const float* __restrict__ rot_mat,
        float* __restrict__ out)
{
    const int tid = threadIdx.x;
    const int bid = blockIdx.x;

    __shared__ float ax[64], ay[64], az[64];
    __shared__ float cf[BKN * 12];        // all 28 (M,d) coefficient sets
    __shared__ float red[8][4];
    __shared__ unsigned sh_gen;

    if (tid == 0) sh_gen = *(volatile unsigned*)&g_gen;   // entry generation
    if (tid < 64) {
        ax[tid] = grids[tid << 12];               // separable meshgrid axes
        ay[tid] = grids[NVOX + (tid << 6)];
        az[tid] = grids[2 * NVOX + tid];
    }
    __syncthreads();
    const unsigned gen0 = sh_gen;

    // ================= Phase 1: weighted sums per (b,k) =================
    // unit u = (bk, chunk); each unit = 2048 float4 = 8 per thread (MLP=8)
    for (int u = bid; u < NUNITS; u += GRID) {
        const int bk    = u >> 5;
        const int chunk = u & 31;
        const int b = bk / 7, k = bk % 7;

        const float4* m4 = (const float4*)(mask + ((size_t)(b * 8 + k)) * NVOX)
                           + (size_t)chunk * 2048;
        const int vbase = chunk * (NVOX / CHUNKS);

        float4 mv[8];
#pragma unroll
        for (int t = 0; t < 8; ++t)
            mv[t] = m4[t * THREADS + tid];

        float s0 = 0.f, sx = 0.f, sy = 0.f, sz = 0.f;
#pragma unroll
        for (int t = 0; t < 8; ++t) {
            const int idx4 = t * THREADS + tid;
            const int v  = vbase + (idx4 << 2);
            const int i  = v >> 12;
            const int j  = (v >> 6) & 63;
            const int kk = v & 63;
            const float ms = (mv[t].x + mv[t].y) + (mv[t].z + mv[t].w);
            s0 += ms;
            sx = fmaf(ax[i], ms, sx);
            sy = fmaf(ay[j], ms, sy);
            sz = fmaf(az[kk],     mv[t].x,
                 fmaf(az[kk + 1], mv[t].y,
                 fmaf(az[kk + 2], mv[t].z,
                 fmaf(az[kk + 3], mv[t].w, sz))));
        }
#pragma unroll
        for (int off = 16; off; off >>= 1) {
            s0 += __shfl_down_sync(0xFFFFFFFFu, s0, off);
            sx += __shfl_down_sync(0xFFFFFFFFu, sx, off);
            sy += __shfl_down_sync(0xFFFFFFFFu, sy, off);
            sz += __shfl_down_sync(0xFFFFFFFFu, sz, off);
        }
        const int w = tid >> 5, l = tid & 31;
        if (l == 0) { red[w][0] = s0; red[w][1] = sx; red[w][2] = sy; red[w][3] = sz; }
        __syncthreads();
        if (tid == 0) {
            float r0 = 0.f, r1 = 0.f, r2 = 0.f, r3 = 0.f;
#pragma unroll
            for (int i = 0; i < 8; ++i) {
                r0 += red[i][0]; r1 += red[i][1]; r2 += red[i][2]; r3 += red[i][3];
            }
            float* p = g_partial + u * 4;
            p[0] = r0; p[1] = r1; p[2] = r2; p[3] = r3;
        }
        __syncthreads();    // red[] reused next unit
    }

    // ================= Grid barrier (single wave guaranteed) =================
    if (tid == 0) {
        __threadfence();                                   // publish partials
        const unsigned arrived = atomicAdd(&g_count, 1u);
        if (arrived == GRID - 1) {
            g_count = 0;                                   // reset for next replay
            __threadfence();
            atomicAdd(&g_gen, 1u);                         // release
        } else {
            while (*(volatile unsigned*)&g_gen == gen0) { }
        }
        __threadfence();                                   // acquire
    }
    __syncthreads();

    // ================= Coefficients: M = R - I, d = p + t - R p =================
    if (tid < BKN) {
        const float* p = g_partial + tid * CHUNKS * 4;
        float s0 = 0.f, sx = 0.f, sy = 0.f, sz = 0.f;
#pragma unroll
        for (int c = 0; c < CHUNKS; ++c) {
            s0 += __ldcg(p + c * 4 + 0); sx += __ldcg(p + c * 4 + 1);
            sy += __ldcg(p + c * 4 + 2); sz += __ldcg(p + c * 4 + 3);
        }
        const float inv = 1.f / s0;
        const float pv[3] = { sx * inv, sy * inv, sz * inv };
        const float* R = rot_mat   + tid * 9;
        const float* t = trans_vec + tid * 3;
        float* c = cf + tid * 12;
#pragma unroll
        for (int r = 0; r < 3; ++r) {
            const float Rp = R[r * 3] * pv[0] + R[r * 3 + 1] * pv[1] + R[r * 3 + 2] * pv[2];
            c[r * 3 + 0] = R[r * 3 + 0] - (r == 0 ? 1.f : 0.f);
            c[r * 3 + 1] = R[r * 3 + 1] - (r == 1 ? 1.f : 0.f);
            c[r * 3 + 2] = R[r * 3 + 2] - (r == 2 ? 1.f : 0.f);
            c[9 + r]     = pv[r] + t[r] - Rp;
        }
    }
    __syncthreads();

    // ================= Phase 2: apply (mask is L2-hot) =================
    // motion[b,c,v] = sum_{k<7} mask[b,k,v] * (M_bk[c,:].g_v + d_bk[c])
    float4* o4 = (float4*)out;
    for (int g = bid * THREADS + tid; g < 4 * (NVOX / 4); g += GRID * THREADS) {
        const int b    = g >> 16;          // NVOX/4 = 65536
        const int idx4 = g & 65535;

        const float4* mb = (const float4*)mask + ((size_t)b * 8) * (NVOX / 4) + idx4;
        float4 mv[7];
#pragma unroll
        for (int k = 0; k < 7; ++k)
            mv[k] = mb[(size_t)k * (NVOX / 4)];

        const int v  = idx4 << 2;
        const int i  = v >> 12;
        const int j  = (v >> 6) & 63;
        const int kk = v & 63;
        const float gx = ax[i], gy = ay[j];
        const float gz[4] = { az[kk], az[kk + 1], az[kk + 2], az[kk + 3] };

        float mot[3][4] = {};
        const float* cb = cf + (b * 7) * 12;
#pragma unroll
        for (int k = 0; k < 7; ++k) {
            const float mvv[4] = { mv[k].x, mv[k].y, mv[k].z, mv[k].w };
            const float* c = cb + k * 12;
#pragma unroll
            for (int cc = 0; cc < 3; ++cc) {
                const float m2   = c[cc * 3 + 2];
                const float base = fmaf(c[cc * 3], gx, fmaf(c[cc * 3 + 1], gy, c[9 + cc]));
#pragma unroll
                for (int t = 0; t < 4; ++t)
                    mot[cc][t] = fmaf(mvv[t], fmaf(m2, gz[t], base), mot[cc][t]);
            }
        }
#pragma unroll
        for (int cc = 0; cc < 3; ++cc) {
            float4 o = { mot[cc][0], mot[cc][1], mot[cc][2], mot[cc][3] };
            o4[((size_t)b * 3 + cc) * (NVOX / 4) + idx4] = o;
        }
    }
}

// ---------------------------------------------------------------------------
extern "C" void kernel_launch(void* const* d_in, const int* in_sizes, int n_in,
                              void* d_out, int out_size)
{
    const float* mask = nullptr;
    const float* tv   = nullptr;
    const float* rm   = nullptr;
    const float* gr   = nullptr;
    for (int i = 0; i < n_in; ++i) {
        switch (in_sizes[i]) {
            case 8388608: mask = (const float*)d_in[i]; break;   // (4,8,64,64,64)
            case 84:      tv   = (const float*)d_in[i]; break;   // (4,7,3)
            case 252:     rm   = (const float*)d_in[i]; break;   // (4,7,3,3)
            case 786432:  gr   = (const float*)d_in[i]; break;   // (3,64,64,64)
        }
    }
    fused_k<<<GRID, THREADS>>>(mask, gr, tv, rm, (float*)d_out);
}

// round 4
// speedup vs baseline: 2.9280x; 2.9280x over previous
#include <cuda_runtime.h>

#define NVOX (64*64*64)        // 262144 voxels
#define BKN 28                 // 4 batches * 7 moving parts
#define CHUNKS 32              // partial-reduction chunks per (b,k)
#define NBLOCKS (BKN * CHUNKS) // 896 reduce blocks
#define RED_THREADS 256
#define APPLY_THREADS 256

// Scratch (no allocations allowed)
__device__ float    g_partial[NBLOCKS * 4];
__device__ float    g_coef[BKN * 12];     // [0..8]=M=R-I row-major, [9..11]=d
__device__ unsigned g_count = 0;          // self-resets every launch

// ---------------------------------------------------------------------------
// Pass 1: per-(b,k) weighted sums (sum m, sum m*gx, sum m*gy, sum m*gz).
// 896 blocks x 256 thr, 8 float4 per thread front-batched (MLP=8).
// The LAST block to finish folds all partials into coefficients:
//   M = R - I,  d = p + t - R p    (partials are L2-hot; fold is parallel)
// ---------------------------------------------------------------------------
__global__ void __launch_bounds__(RED_THREADS)
reduce_k(const float* __restrict__ mask, const float* __restrict__ grids,
         const float* __restrict__ trans_vec, const float* __restrict__ rot_mat)
{
    const int bk    = blockIdx.x >> 5;     // / CHUNKS
    const int chunk = blockIdx.x & 31;     // % CHUNKS
    const int b = bk / 7, k = bk % 7;
    const int tid = threadIdx.x;

    __shared__ float ax[64], ay[64], az[64];
    __shared__ float red[8][4];
    __shared__ float fold[BKN][4];
    __shared__ bool  is_last;

    if (tid < 64) {
        ax[tid] = grids[tid << 12];                 // gx[i,0,0]
        ay[tid] = grids[NVOX + (tid << 6)];         // gy[0,j,0]
        az[tid] = grids[2 * NVOX + tid];            // gz[0,0,k]
    }

    const float4* m4 = (const float4*)(mask + ((size_t)(b * 8 + k)) * NVOX)
                       + (size_t)chunk * 2048;
    const int vbase = chunk * (NVOX / CHUNKS);

    // issue all 8 loads before consuming (MLP=8)
    float4 mv[8];
#pragma unroll
    for (int t = 0; t < 8; ++t)
        mv[t] = m4[t * RED_THREADS + tid];

    __syncthreads();   // axes ready

    float s0 = 0.f, sx = 0.f, sy = 0.f, sz = 0.f;
#pragma unroll
    for (int t = 0; t < 8; ++t) {
        const int idx4 = t * RED_THREADS + tid;
        const int v  = vbase + (idx4 << 2);
        const int i  = v >> 12;
        const int j  = (v >> 6) & 63;
        const int kk = v & 63;
        const float ms = (mv[t].x + mv[t].y) + (mv[t].z + mv[t].w);
        s0 += ms;
        sx = fmaf(ax[i], ms, sx);
        sy = fmaf(ay[j], ms, sy);
        sz = fmaf(az[kk],     mv[t].x,
             fmaf(az[kk + 1], mv[t].y,
             fmaf(az[kk + 2], mv[t].z,
             fmaf(az[kk + 3], mv[t].w, sz))));
    }

    // warp tree reduce (deterministic)
#pragma unroll
    for (int off = 16; off; off >>= 1) {
        s0 += __shfl_down_sync(0xFFFFFFFFu, s0, off);
        sx += __shfl_down_sync(0xFFFFFFFFu, sx, off);
        sy += __shfl_down_sync(0xFFFFFFFFu, sy, off);
        sz += __shfl_down_sync(0xFFFFFFFFu, sz, off);
    }
    const int w = tid >> 5, l = tid & 31;
    if (l == 0) { red[w][0] = s0; red[w][1] = sx; red[w][2] = sy; red[w][3] = sz; }
    __syncthreads();
    if (tid == 0) {
        float r0 = 0.f, r1 = 0.f, r2 = 0.f, r3 = 0.f;
#pragma unroll
        for (int i = 0; i < 8; ++i) {
            r0 += red[i][0]; r1 += red[i][1]; r2 += red[i][2]; r3 += red[i][3];
        }
        float* p = g_partial + blockIdx.x * 4;
        p[0] = r0; p[1] = r1; p[2] = r2; p[3] = r3;
        __threadfence();                                // publish partial
        const unsigned arrived = atomicAdd(&g_count, 1u);
        is_last = (arrived == NBLOCKS - 1);
        if (is_last) g_count = 0;                       // reset for next replay
    }
    __syncthreads();
    if (!is_last) return;

    // -------- last block: fold partials -> coefficients (L2-hot) --------
    if (tid < BKN * 4) {                 // 112 threads: one (bk, component) each
        const int fbk  = tid >> 2;
        const int comp = tid & 3;
        const float* p = g_partial + (fbk * CHUNKS) * 4 + comp;
        float s = 0.f;
#pragma unroll
        for (int c = 0; c < CHUNKS; ++c)
            s += __ldcg(p + c * 4);
        fold[fbk][comp] = s;
    }
    __syncthreads();
    if (tid < BKN) {
        const float inv = 1.f / fold[tid][0];
        const float pv[3] = { fold[tid][1] * inv, fold[tid][2] * inv, fold[tid][3] * inv };
        const float* R = rot_mat   + tid * 9;
        const float* t = trans_vec + tid * 3;
        float* c = g_coef + tid * 12;
#pragma unroll
        for (int r = 0; r < 3; ++r) {
            const float Rp = R[r * 3] * pv[0] + R[r * 3 + 1] * pv[1] + R[r * 3 + 2] * pv[2];
            c[r * 3 + 0] = R[r * 3 + 0] - (r == 0 ? 1.f : 0.f);
            c[r * 3 + 1] = R[r * 3 + 1] - (r == 1 ? 1.f : 0.f);
            c[r * 3 + 2] = R[r * 3 + 2] - (r == 2 ? 1.f : 0.f);
            c[9 + r]     = pv[r] + t[r] - Rp;
        }
    }
}

// ---------------------------------------------------------------------------
// Pass 2: motion[b,c,v] = sum_{k<7} mask[b,k,v] * (M_bk[c,:].g_v + d_bk[c])
// Coefficients are precomputed; mask slabs are L2-hot from pass 1.
// ---------------------------------------------------------------------------
__global__ void __launch_bounds__(APPLY_THREADS)
apply_k(const float* __restrict__ mask, const float* __restrict__ grids,
        float* __restrict__ out)
{
    const int blocksPerB = NVOX / 4 / APPLY_THREADS;   // 256
    const int b   = blockIdx.x / blocksPerB;
    const int blk = blockIdx.x % blocksPerB;
    const int tid = threadIdx.x;

    __shared__ float cf[84];            // 7 * 12 coefficients for this batch
    __shared__ float ax[64], ay[64], az[64];
    if (tid < 84) cf[tid] = g_coef[b * 84 + tid];      // one broadcast load each
    if (tid < 64) {
        ax[tid] = grids[tid << 12];
        ay[tid] = grids[NVOX + (tid << 6)];
        az[tid] = grids[2 * NVOX + tid];
    }

    const int idx4 = blk * APPLY_THREADS + tid;
    const float4* mb = (const float4*)mask + ((size_t)b * 8) * (NVOX / 4) + idx4;

    // issue all 7 mask loads before consuming (MLP=7)
    float4 mv[7];
#pragma unroll
    for (int k = 0; k < 7; ++k)
        mv[k] = mb[(size_t)k * (NVOX / 4)];

    __syncthreads();   // cf + axes ready

    const int v  = idx4 << 2;
    const int i  = v >> 12;
    const int j  = (v >> 6) & 63;
    const int kk = v & 63;
    const float gx = ax[i], gy = ay[j];
    const float gz[4] = { az[kk], az[kk + 1], az[kk + 2], az[kk + 3] };

    float mot[3][4] = {};
#pragma unroll
    for (int k = 0; k < 7; ++k) {
        const float mvv[4] = { mv[k].x, mv[k].y, mv[k].z, mv[k].w };
        const float* c = cf + k * 12;
#pragma unroll
        for (int cc = 0; cc < 3; ++cc) {
            const float m2   = c[cc * 3 + 2];
            const float base = fmaf(c[cc * 3], gx, fmaf(c[cc * 3 + 1], gy, c[9 + cc]));
#pragma unroll
            for (int t = 0; t < 4; ++t)
                mot[cc][t] = fmaf(mvv[t], fmaf(m2, gz[t], base), mot[cc][t]);
        }
    }

    float4* o4 = (float4*)out;
#pragma unroll
    for (int cc = 0; cc < 3; ++cc) {
        float4 o = { mot[cc][0], mot[cc][1], mot[cc][2], mot[cc][3] };
        o4[((size_t)b * 3 + cc) * (NVOX / 4) + idx4] = o;
    }
}

// ---------------------------------------------------------------------------
extern "C" void kernel_launch(void* const* d_in, const int* in_sizes, int n_in,
                              void* d_out, int out_size)
{
    const float* mask = nullptr;
    const float* tv   = nullptr;
    const float* rm   = nullptr;
    const float* gr   = nullptr;
    for (int i = 0; i < n_in; ++i) {
        switch (in_sizes[i]) {
            case 8388608: mask = (const float*)d_in[i]; break;   // (4,8,64,64,64)
            case 84:      tv   = (const float*)d_in[i]; break;   // (4,7,3)
            case 252:     rm   = (const float*)d_in[i]; break;   // (4,7,3,3)
            case 786432:  gr   = (const float*)d_in[i]; break;   // (3,64,64,64)
        }
    }
    reduce_k<<<NBLOCKS, RED_THREADS>>>(mask, gr, tv, rm);
    apply_k<<<4 * (NVOX / 4 / APPLY_THREADS), APPLY_THREADS>>>(mask, gr, (float*)d_out);
}